// round 3
// baseline (speedup 1.0000x reference)
#include <cuda_runtime.h>
#include <math.h>
#include <stdint.h>

#define Bc    2
#define Tc    2048
#define Ec    2048
#define Hc    16
#define HKVc  4
#define Mc    4
#define HDc   32
#define DVc   128
#define BTc   (Bc*Tc)      // 4096
#define KVE   512

// ---------------- scratch (device globals; no allocations allowed) ----------
__device__ float g_q[(size_t)BTc * Ec];     // Q proj (B,T,64,32)
__device__ float g_k[(size_t)BTc * KVE];    // K proj (B,T,16,32)
__device__ float g_v[(size_t)BTc * KVE];    // V proj (B,T,4,128)
__device__ float g_comb[(size_t)BTc * Ec];  // normed combined (B,T,H,128)

// =====================================================================
// tf32 split: v = hi + lo with hi = round-to-tf32(v).  3-pass mma
// (hi*hi + lo*hi + hi*lo) recovers ~fp32 accuracy.
// =====================================================================
__device__ __forceinline__ float2 tf32_split(float v) {
    uint32_t hb;
    asm("cvt.rna.tf32.f32 %0, %1;" : "=r"(hb) : "f"(v));
    float hf = __uint_as_float(hb);
    return make_float2(hf, v - hf);
}

#define MMA_TF32(D, Ar, Br)                                                   \
    asm volatile(                                                             \
        "mma.sync.aligned.m16n8k8.row.col.f32.tf32.tf32.f32 "                 \
        "{%0,%1,%2,%3},{%4,%5,%6,%7},{%8,%9},{%0,%1,%2,%3};"                  \
        : "+f"(D[0]), "+f"(D[1]), "+f"(D[2]), "+f"(D[3])                      \
        : "r"(Ar[0]), "r"(Ar[1]), "r"(Ar[2]), "r"(Ar[3]),                     \
          "r"(Br[0]), "r"(Br[1]))

// =====================================================================
// Tensor-core GEMM:  C[.,N] = A[.,K] * W[N,K]^T   (row-major, K contig)
// 128x128 block tile, BK=16, 256 threads (8 warps, 4m x 2n),
// warp tile 32x64 via m16n8k8 tf32 fragments, hi/lo packed as float2.
// blockIdx.z selects (W0,C0)/(W1,C1) so two GEMMs share one launch.
// =====================================================================
#define KB  16
#define AST 132      // float2 per k-row (128 + 4 pad)

__global__ __launch_bounds__(256) void mma_gemm_nt(
    const float* __restrict__ A,
    const float* __restrict__ W0, float* __restrict__ C0,
    const float* __restrict__ W1, float* __restrict__ C1,
    int N, int K)
{
    const float* W = (blockIdx.z == 0) ? W0 : W1;
    float*       C = (blockIdx.z == 0) ? C0 : C1;

    __shared__ float2 As[KB * AST];
    __shared__ float2 Bs[KB * AST];

    const int tid  = threadIdx.x;
    const int lane = tid & 31;
    const int warp = tid >> 5;
    const int wm   = warp & 3;          // m block of 32
    const int wn   = warp >> 2;         // n block of 64
    const int grp  = lane >> 2;         // 0..7
    const int tig  = lane & 3;          // 0..3

    const int r  = tid >> 1;            // 0..127 staging row
    const int kq = (tid & 1) * 8;       // staging k offset

    const float* Ap = A + (size_t)(blockIdx.y * 128 + r) * K + kq;
    const float* Wp = W + (size_t)(blockIdx.x * 128 + r) * K + kq;

    float d[2][8][4];
#pragma unroll
    for (int f = 0; f < 2; f++)
#pragma unroll
        for (int g = 0; g < 8; g++)
#pragma unroll
            for (int e = 0; e < 4; e++) d[f][g][e] = 0.f;

    float4 pa0 = *(const float4*)(Ap);
    float4 pa1 = *(const float4*)(Ap + 4);
    float4 pw0 = *(const float4*)(Wp);
    float4 pw1 = *(const float4*)(Wp + 4);

    const int nkt = K / KB;
    for (int kt = 0; kt < nkt; kt++) {
        // ---- stage with tf32 split (hi,lo interleaved) ----
        {
            float2* ad = As + kq * AST + r;
            float2* bd = Bs + kq * AST + r;
            ad[0 * AST] = tf32_split(pa0.x); ad[1 * AST] = tf32_split(pa0.y);
            ad[2 * AST] = tf32_split(pa0.z); ad[3 * AST] = tf32_split(pa0.w);
            ad[4 * AST] = tf32_split(pa1.x); ad[5 * AST] = tf32_split(pa1.y);
            ad[6 * AST] = tf32_split(pa1.z); ad[7 * AST] = tf32_split(pa1.w);
            bd[0 * AST] = tf32_split(pw0.x); bd[1 * AST] = tf32_split(pw0.y);
            bd[2 * AST] = tf32_split(pw0.z); bd[3 * AST] = tf32_split(pw0.w);
            bd[4 * AST] = tf32_split(pw1.x); bd[5 * AST] = tf32_split(pw1.y);
            bd[6 * AST] = tf32_split(pw1.z); bd[7 * AST] = tf32_split(pw1.w);
        }
        __syncthreads();
        if (kt + 1 < nkt) {
            pa0 = *(const float4*)(Ap + (kt + 1) * KB);
            pa1 = *(const float4*)(Ap + (kt + 1) * KB + 4);
            pw0 = *(const float4*)(Wp + (kt + 1) * KB);
            pw1 = *(const float4*)(Wp + (kt + 1) * KB + 4);
        }

#pragma unroll
        for (int ks = 0; ks < KB; ks += 8) {
            uint32_t Ahi[2][4], Alo[2][4];
#pragma unroll
            for (int f = 0; f < 2; f++) {
                const int m = wm * 32 + f * 16 + grp;
                float2 p0 = As[(ks + tig) * AST + m];
                float2 p1 = As[(ks + tig) * AST + m + 8];
                float2 p2 = As[(ks + tig + 4) * AST + m];
                float2 p3 = As[(ks + tig + 4) * AST + m + 8];
                Ahi[f][0] = __float_as_uint(p0.x); Alo[f][0] = __float_as_uint(p0.y);
                Ahi[f][1] = __float_as_uint(p1.x); Alo[f][1] = __float_as_uint(p1.y);
                Ahi[f][2] = __float_as_uint(p2.x); Alo[f][2] = __float_as_uint(p2.y);
                Ahi[f][3] = __float_as_uint(p3.x); Alo[f][3] = __float_as_uint(p3.y);
            }
#pragma unroll
            for (int g = 0; g < 8; g++) {
                const int n = wn * 64 + g * 8 + grp;
                float2 q0 = Bs[(ks + tig) * AST + n];
                float2 q1 = Bs[(ks + tig + 4) * AST + n];
                uint32_t Bh[2] = {__float_as_uint(q0.x), __float_as_uint(q1.x)};
                uint32_t Bl[2] = {__float_as_uint(q0.y), __float_as_uint(q1.y)};
#pragma unroll
                for (int f = 0; f < 2; f++) {
                    MMA_TF32(d[f][g], Ahi[f], Bh);
                    MMA_TF32(d[f][g], Alo[f], Bh);
                    MMA_TF32(d[f][g], Ahi[f], Bl);
                }
            }
        }
        __syncthreads();
    }

    // ---- epilogue ----
#pragma unroll
    for (int f = 0; f < 2; f++) {
        const int mrow = blockIdx.y * 128 + wm * 32 + f * 16 + grp;
#pragma unroll
        for (int g = 0; g < 8; g++) {
            const int ncol = blockIdx.x * 128 + wn * 64 + g * 8 + 2 * tig;
            *(float2*)(C + (size_t)mrow * N + ncol) =
                make_float2(d[f][g][0], d[f][g][1]);
            *(float2*)(C + (size_t)(mrow + 8) * N + ncol) =
                make_float2(d[f][g][2], d[f][g][3]);
        }
    }
}

// =====================================================================
// Interleaved RoPE in-place on (BT, nh, 32).
// =====================================================================
__global__ void rope_kernel(float* __restrict__ x,
                            const float* __restrict__ cs,
                            const float* __restrict__ sn, int nh)
{
    int idx = blockIdx.x * 256 + threadIdx.x;
    int total = BTc * nh * (HDc / 2);
    if (idx >= total) return;
    int p    = idx & (HDc / 2 - 1);
    int rest = idx >> 4;
    int h    = rest % nh;
    int row  = rest / nh;
    int t    = row & (Tc - 1);
    float c = cs[t * (HDc / 2) + p];
    float s = sn[t * (HDc / 2) + p];
    float* ptr = x + ((size_t)row * nh + h) * HDc + 2 * p;
    float x1 = ptr[0], x2 = ptr[1];
    ptr[0] = x1 * c - x2 * s;
    ptr[1] = x1 * s + x2 * c;
}

// =====================================================================
// Fused 4-ensemble flash attention + RMSNorm (unchanged from R2).
// =====================================================================
#define QS        (64*33)
#define SQ_FLOATS (4*QS)
#define SP_STRIDE 66
#define SP_FLOATS (64*SP_STRIDE)
#define SV_FLOATS (64*128)
#define X_FLOATS  (SP_FLOATS + SV_FLOATS)
#define FL_SMEM   ((SQ_FLOATS + X_FLOATS + 2*4*64) * 4)

__global__ __launch_bounds__(256, 2) void flash_kernel(
    const float* __restrict__ Q, const float* __restrict__ Kb,
    const float* __restrict__ Vb, const float* __restrict__ rawmap,
    const float* __restrict__ wscale, const float* __restrict__ gamma,
    float* __restrict__ Out)
{
    extern __shared__ float sm[];
    float* sQ   = sm;
    float* sX   = sm + SQ_FLOATS;
    float* sStM = sX + X_FLOATS;
    float* sStI = sStM + 4 * 64;

    const int qt  = gridDim.x - 1 - blockIdx.x;
    const int h   = blockIdx.y;
    const int b   = blockIdx.z;
    const int hkv = h >> 2;
    const int tid = threadIdx.x;
    const int tx  = tid & 15;
    const int ty  = tid >> 4;
    const int tx4 = tx * 4;
    const int ty4 = ty * 4;
    const int q0  = qt * 64;
    const float scale = 0.17677669529663687f;

#pragma unroll
    for (int u = 0; u < 8; u++) {
        int fi = u * 256 + tid;
        int m  = fi >> 9;
        int lr = (fi >> 3) & 63;
        int c4 = (fi & 7) * 4;
        float4 v4 = *(const float4*)(Q +
            ((size_t)(b * Tc + q0 + lr) * 64 + (h * 4 + m)) * HDc + c4);
        float* dst = sQ + m * QS + lr * 33 + c4;
        dst[0] = v4.x; dst[1] = v4.y; dst[2] = v4.z; dst[3] = v4.w;
    }

    float mapw[4];
#pragma unroll
    for (int m = 0; m < 4; m++) mapw[m] = tanhf(rawmap[m]) * wscale[0];

    float RM[4][4], RS[4][4];
#pragma unroll
    for (int m = 0; m < 4; m++)
#pragma unroll
        for (int r = 0; r < 4; r++) { RM[m][r] = -1e30f; RS[m][r] = 0.f; }

    for (int jt = 0; jt <= qt; jt++) {
        const int k0 = jt * 64;
        __syncthreads();
#pragma unroll
        for (int u = 0; u < 8; u++) {
            int fi = u * 256 + tid;
            int m  = fi >> 9;
            int lr = (fi >> 3) & 63;
            int c4 = (fi & 7) * 4;
            float4 v4 = *(const float4*)(Kb +
                ((size_t)(b * Tc + k0 + lr) * 16 + (hkv * 4 + m)) * HDc + c4);
            float* dst = sX + m * QS + lr * 33 + c4;
            dst[0] = v4.x; dst[1] = v4.y; dst[2] = v4.z; dst[3] = v4.w;
        }
        __syncthreads();
        const bool diag = (jt == qt);

        for (int m = 0; m < 4; m++) {
            const float* Qp = sQ + m * QS + ty4 * 33;
            const float* Kp = sX + m * QS + tx4 * 33;
            float S[4][4];
#pragma unroll
            for (int r = 0; r < 4; r++)
#pragma unroll
                for (int c = 0; c < 4; c++) S[r][c] = 0.f;
#pragma unroll 8
            for (int d = 0; d < 32; d++) {
                float a0 = Qp[d], a1 = Qp[33 + d], a2 = Qp[66 + d], a3 = Qp[99 + d];
                float b0 = Kp[d], b1 = Kp[33 + d], b2 = Kp[66 + d], b3 = Kp[99 + d];
                S[0][0] += a0 * b0; S[0][1] += a0 * b1; S[0][2] += a0 * b2; S[0][3] += a0 * b3;
                S[1][0] += a1 * b0; S[1][1] += a1 * b1; S[1][2] += a1 * b2; S[1][3] += a1 * b3;
                S[2][0] += a2 * b0; S[2][1] += a2 * b1; S[2][2] += a2 * b2; S[2][3] += a2 * b3;
                S[3][0] += a3 * b0; S[3][1] += a3 * b1; S[3][2] += a3 * b2; S[3][3] += a3 * b3;
            }
#pragma unroll
            for (int r = 0; r < 4; r++) {
#pragma unroll
                for (int c = 0; c < 4; c++) {
                    float s = S[r][c] * scale;
                    if (diag && (k0 + tx4 + c > q0 + ty4 + r)) s = -1e30f;
                    S[r][c] = s;
                }
                float tm = fmaxf(fmaxf(S[r][0], S[r][1]), fmaxf(S[r][2], S[r][3]));
#pragma unroll
                for (int o = 1; o < 16; o <<= 1)
                    tm = fmaxf(tm, __shfl_xor_sync(0xffffffffu, tm, o));
                float mnew = fmaxf(RM[m][r], tm);
                float corr = __expf(RM[m][r] - mnew);
                float ps = __expf(S[r][0] - mnew) + __expf(S[r][1] - mnew)
                         + __expf(S[r][2] - mnew) + __expf(S[r][3] - mnew);
#pragma unroll
                for (int o = 1; o < 16; o <<= 1)
                    ps += __shfl_xor_sync(0xffffffffu, ps, o);
                RS[m][r] = RS[m][r] * corr + ps;
                RM[m][r] = mnew;
            }
        }
    }

    __syncthreads();
    if (tx == 0) {
#pragma unroll
        for (int m = 0; m < 4; m++)
#pragma unroll
            for (int r = 0; r < 4; r++) {
                sStM[m * 64 + ty4 + r] = RM[m][r];
                sStI[m * 64 + ty4 + r] = mapw[m] / RS[m][r];
            }
    }
    __syncthreads();

    float acc[4][8];
#pragma unroll
    for (int r = 0; r < 4; r++)
#pragma unroll
        for (int c = 0; c < 8; c++) acc[r][c] = 0.f;

    for (int jt = 0; jt <= qt; jt++) {
        const int k0 = jt * 64;
        __syncthreads();
#pragma unroll
        for (int u = 0; u < 8; u++) {
            int fi = u * 256 + tid;
            int m  = fi >> 9;
            int lr = (fi >> 3) & 63;
            int c4 = (fi & 7) * 4;
            float4 v4 = *(const float4*)(Kb +
                ((size_t)(b * Tc + k0 + lr) * 16 + (hkv * 4 + m)) * HDc + c4);
            float* dst = sX + m * QS + lr * 33 + c4;
            dst[0] = v4.x; dst[1] = v4.y; dst[2] = v4.z; dst[3] = v4.w;
        }
        __syncthreads();
        const bool diag = (jt == qt);

        float P[4][4];
#pragma unroll
        for (int r = 0; r < 4; r++)
#pragma unroll
            for (int c = 0; c < 4; c++) P[r][c] = 0.f;

        for (int m = 0; m < 4; m++) {
            const float* Qp = sQ + m * QS + ty4 * 33;
            const float* Kp = sX + m * QS + tx4 * 33;
            float S[4][4];
#pragma unroll
            for (int r = 0; r < 4; r++)
#pragma unroll
                for (int c = 0; c < 4; c++) S[r][c] = 0.f;
#pragma unroll 8
            for (int d = 0; d < 32; d++) {
                float a0 = Qp[d], a1 = Qp[33 + d], a2 = Qp[66 + d], a3 = Qp[99 + d];
                float b0 = Kp[d], b1 = Kp[33 + d], b2 = Kp[66 + d], b3 = Kp[99 + d];
                S[0][0] += a0 * b0; S[0][1] += a0 * b1; S[0][2] += a0 * b2; S[0][3] += a0 * b3;
                S[1][0] += a1 * b0; S[1][1] += a1 * b1; S[1][2] += a1 * b2; S[1][3] += a1 * b3;
                S[2][0] += a2 * b0; S[2][1] += a2 * b1; S[2][2] += a2 * b2; S[2][3] += a2 * b3;
                S[3][0] += a3 * b0; S[3][1] += a3 * b1; S[3][2] += a3 * b2; S[3][3] += a3 * b3;
            }
#pragma unroll
            for (int r = 0; r < 4; r++) {
                float sm_ = sStM[m * 64 + ty4 + r];
                float si  = sStI[m * 64 + ty4 + r];
#pragma unroll
                for (int c = 0; c < 4; c++) {
                    float s = S[r][c] * scale;
                    if (diag && (k0 + tx4 + c > q0 + ty4 + r)) s = -1e30f;
                    P[r][c] += si * __expf(s - sm_);
                }
            }
        }
        __syncthreads();

#pragma unroll
        for (int r = 0; r < 4; r++)
#pragma unroll
            for (int c = 0; c < 4; c++)
                sX[(ty4 + r) * SP_STRIDE + tx4 + c] = P[r][c];
#pragma unroll
        for (int u = 0; u < 8; u++) {
            int fi = u * 256 + tid;
            int lr = fi >> 5;
            int c4 = (fi & 31) * 4;
            *(float4*)(sX + SP_FLOATS + lr * 128 + c4) = *(const float4*)(Vb +
                ((size_t)(b * Tc + k0 + lr) * HKVc + hkv) * DVc + c4);
        }
        __syncthreads();

        const float* Pp = sX + ty4 * SP_STRIDE;
        const float* Vp = sX + SP_FLOATS;
#pragma unroll 8
        for (int kk = 0; kk < 64; kk++) {
            float a0 = Pp[kk], a1 = Pp[SP_STRIDE + kk],
                  a2 = Pp[2 * SP_STRIDE + kk], a3 = Pp[3 * SP_STRIDE + kk];
            float4 bl = *(const float4*)(Vp + kk * 128 + tx4);
            float4 bh = *(const float4*)(Vp + kk * 128 + 64 + tx4);
            acc[0][0] += a0 * bl.x; acc[0][1] += a0 * bl.y; acc[0][2] += a0 * bl.z; acc[0][3] += a0 * bl.w;
            acc[0][4] += a0 * bh.x; acc[0][5] += a0 * bh.y; acc[0][6] += a0 * bh.z; acc[0][7] += a0 * bh.w;
            acc[1][0] += a1 * bl.x; acc[1][1] += a1 * bl.y; acc[1][2] += a1 * bl.z; acc[1][3] += a1 * bl.w;
            acc[1][4] += a1 * bh.x; acc[1][5] += a1 * bh.y; acc[1][6] += a1 * bh.z; acc[1][7] += a1 * bh.w;
            acc[2][0] += a2 * bl.x; acc[2][1] += a2 * bl.y; acc[2][2] += a2 * bl.z; acc[2][3] += a2 * bl.w;
            acc[2][4] += a2 * bh.x; acc[2][5] += a2 * bh.y; acc[2][6] += a2 * bh.z; acc[2][7] += a2 * bh.w;
            acc[3][0] += a3 * bl.x; acc[3][1] += a3 * bl.y; acc[3][2] += a3 * bl.z; acc[3][3] += a3 * bl.w;
            acc[3][4] += a3 * bh.x; acc[3][5] += a3 * bh.y; acc[3][6] += a3 * bh.z; acc[3][7] += a3 * bh.w;
        }
    }

    float4 g0 = *(const float4*)(gamma + tx4);
    float4 g1 = *(const float4*)(gamma + 64 + tx4);
#pragma unroll
    for (int r = 0; r < 4; r++) {
        float ss = 0.f;
#pragma unroll
        for (int c = 0; c < 8; c++) ss += acc[r][c] * acc[r][c];
#pragma unroll
        for (int o = 1; o < 16; o <<= 1)
            ss += __shfl_xor_sync(0xffffffffu, ss, o);
        float rs = rsqrtf(ss * (1.f / 128.f) + 1e-5f);
        float* dst = Out + ((size_t)(b * Tc + q0 + ty4 + r) * Hc + h) * DVc;
        *(float4*)(dst + tx4) = make_float4(
            acc[r][0] * rs * g0.x, acc[r][1] * rs * g0.y,
            acc[r][2] * rs * g0.z, acc[r][3] * rs * g0.w);
        *(float4*)(dst + 64 + tx4) = make_float4(
            acc[r][4] * rs * g1.x, acc[r][5] * rs * g1.y,
            acc[r][6] * rs * g1.z, acc[r][7] * rs * g1.w);
    }
}

// =====================================================================
extern "C" void kernel_launch(void* const* d_in, const int* in_sizes, int n_in,
                              void* d_out, int out_size)
{
    (void)in_sizes; (void)n_in; (void)out_size;
    const float* x      = (const float*)d_in[0];
    const float* cosb   = (const float*)d_in[1];
    const float* sinb   = (const float*)d_in[2];
    const float* q_w    = (const float*)d_in[3];
    const float* k_w    = (const float*)d_in[4];
    const float* v_w    = (const float*)d_in[5];
    const float* out_w  = (const float*)d_in[6];
    const float* rawmap = (const float*)d_in[7];
    const float* wscale = (const float*)d_in[8];
    const float* gamma  = (const float*)d_in[9];

    float *qp, *kp, *vp, *cp;
    cudaGetSymbolAddress((void**)&qp, g_q);
    cudaGetSymbolAddress((void**)&kp, g_k);
    cudaGetSymbolAddress((void**)&vp, g_v);
    cudaGetSymbolAddress((void**)&cp, g_comb);

    cudaFuncSetAttribute(flash_kernel,
                         cudaFuncAttributeMaxDynamicSharedMemorySize, FL_SMEM);

    // Q projection
    mma_gemm_nt<<<dim3(Ec / 128, BTc / 128, 1), 256>>>(x, q_w, qp, q_w, qp, Ec, Ec);
    // K and V projections fused in one launch
    mma_gemm_nt<<<dim3(KVE / 128, BTc / 128, 2), 256>>>(x, k_w, kp, v_w, vp, KVE, Ec);

    // RoPE
    {
        int tq = BTc * (Hc * Mc) * (HDc / 2);
        int tk = BTc * (HKVc * Mc) * (HDc / 2);
        rope_kernel<<<(tq + 255) / 256, 256>>>(qp, cosb, sinb, Hc * Mc);
        rope_kernel<<<(tk + 255) / 256, 256>>>(kp, cosb, sinb, HKVc * Mc);
    }

    // Fused 4-ensemble flash attention + RMSNorm
    flash_kernel<<<dim3(Tc / 64, Hc, Bc), 256, FL_SMEM>>>(
        qp, kp, vp, rawmap, wscale, gamma, cp);

    // Output projection
    mma_gemm_nt<<<dim3(Ec / 128, BTc / 128, 1), 256>>>(cp, out_w, (float*)d_out,
                                                       out_w, (float*)d_out, Ec, Ec);
}

// round 5
// speedup vs baseline: 1.5344x; 1.5344x over previous
#include <cuda_runtime.h>
#include <cuda_fp16.h>
#include <math.h>
#include <stdint.h>

#define Bc    2
#define Tc    2048
#define Ec    2048
#define Hc    16
#define HKVc  4
#define Mc    4
#define HDc   32
#define DVc   128
#define BTc   (Bc*Tc)      // 4096
#define KVE   512

// ---------------- scratch (device globals; no allocations allowed) ----------
__device__ float g_q[(size_t)BTc * Ec];     // Q proj (B,T,64,32)
__device__ float g_k[(size_t)BTc * KVE];    // K proj (B,T,16,32)
__device__ float g_v[(size_t)BTc * KVE];    // V proj (B,T,4,128)
__device__ float g_comb[(size_t)BTc * Ec];  // normed combined (B,T,H,128)

// 2-limb fp16 splits (limb p at offset p*plane)
__device__ __align__(16) __half g_x2[(size_t)2 * BTc * Ec];   // x / comb limbs
__device__ __align__(16) __half g_wq2[(size_t)2 * Ec * Ec];
__device__ __align__(16) __half g_wk2[(size_t)2 * KVE * Ec];
__device__ __align__(16) __half g_wv2[(size_t)2 * KVE * Ec];
__device__ __align__(16) __half g_wo2[(size_t)2 * Ec * Ec];

// ================= PTX helpers =================
__device__ __forceinline__ uint32_t smem_u32(const void* p) {
    uint32_t a;
    asm("{ .reg .u64 t; cvta.to.shared.u64 t, %1; cvt.u32.u64 %0, t; }"
        : "=r"(a) : "l"(p));
    return a;
}
#define LDSM_X4(r, addr)                                                       \
    asm volatile("ldmatrix.sync.aligned.m8n8.x4.shared.b16 {%0,%1,%2,%3}, [%4];" \
        : "=r"((r)[0]), "=r"((r)[1]), "=r"((r)[2]), "=r"((r)[3]) : "r"(addr))
#define MMA16816(D, A, b0, b1)                                                 \
    asm volatile("mma.sync.aligned.m16n8k16.row.col.f32.f16.f16.f32 "          \
        "{%0,%1,%2,%3},{%4,%5,%6,%7},{%8,%9},{%0,%1,%2,%3};"                   \
        : "+f"((D)[0]), "+f"((D)[1]), "+f"((D)[2]), "+f"((D)[3])               \
        : "r"((A)[0]), "r"((A)[1]), "r"((A)[2]), "r"((A)[3]), "r"(b0), "r"(b1))
#define CP_ASYNC16(saddr, gaddr)                                               \
    asm volatile("cp.async.cg.shared.global [%0], [%1], 16;"                   \
        :: "r"(saddr), "l"(gaddr) : "memory")
#define CP_COMMIT()  asm volatile("cp.async.commit_group;" ::: "memory")
#define CP_WAIT1()   asm volatile("cp.async.wait_group 1;" ::: "memory")
#define CP_WAIT0()   asm volatile("cp.async.wait_group 0;" ::: "memory")

// =====================================================================
// split2: fp32 -> 2 fp16 limbs (h, l), planes at p*plane.
// =====================================================================
__global__ void split2_kernel(const float* __restrict__ src,
                              __half* __restrict__ dst,
                              size_t n2, size_t plane)
{
    size_t i = (size_t)blockIdx.x * blockDim.x + threadIdx.x;
    if (i >= n2) return;
    float2 v = *(const float2*)(src + i * 2);
    __half h0 = __float2half_rn(v.x);
    __half h1 = __float2half_rn(v.y);
    __half l0 = __float2half_rn(v.x - __half2float(h0));
    __half l1 = __float2half_rn(v.y - __half2float(h1));
    *(__half2*)(dst + i * 2)         = __halves2half2(h0, h1);
    *(__half2*)(dst + plane + i * 2) = __halves2half2(l0, l1);
}

// =====================================================================
// fp16 3-pass HMMA GEMM:  C[.,N] = A[.,K] * W[N,K]^T  (~fp32 accuracy)
// 128x128 tile, BK=64 halves (128B rows, SW128 swizzle), 256 threads,
// 8 warps (4m x 2n), warp tile 32x64, m16n8k16 via ldmatrix.x4,
// cp.async 2-stage double buffering.  blockIdx.z selects (Wa,Ca)/(Wb,Cb).
// =====================================================================
#define GBK      64
#define PLANE_B  16384                 // 128 rows * 128 B
#define STAGE_B  (4 * PLANE_B)         // Ah | Al | Wh | Wl
#define G_SMEM   (2 * STAGE_B)         // 131072 B

__global__ __launch_bounds__(256) void hgemm3(
    const __half* __restrict__ A2, size_t aplane,
    const __half* __restrict__ Wa2, float* __restrict__ Ca,
    const __half* __restrict__ Wb2, float* __restrict__ Cb,
    int N, int K)
{
    const __half* W2 = blockIdx.z ? Wb2 : Wa2;
    float*        C  = blockIdx.z ? Cb  : Ca;
    const size_t wplane = (size_t)N * K;

    extern __shared__ char smem[];
    const uint32_t sb = smem_u32(smem);
    const int tid  = threadIdx.x;
    const int lane = tid & 31;
    const int warp = tid >> 5;
    const int wm   = warp & 3;
    const int wn   = warp >> 2;
    const int row0 = blockIdx.y * 128;
    const int col0 = blockIdx.x * 128;

    // ---- staging (cp.async) ----
    const int lrow = tid >> 1;
    const int ucb  = (tid & 1) * 4;
    const __half* srcs[4] = {
        A2 +            (size_t)(row0 + lrow) * K,
        A2 + aplane   + (size_t)(row0 + lrow) * K,
        W2 +            (size_t)(col0 + lrow) * K,
        W2 + wplane   + (size_t)(col0 + lrow) * K };
    uint32_t dsts[4][4];
#pragma unroll
    for (int p = 0; p < 4; p++)
#pragma unroll
        for (int j = 0; j < 4; j++) {
            uint32_t off = (uint32_t)lrow * 128 + (ucb + j) * 16;
            dsts[p][j] = p * PLANE_B + (off ^ ((off >> 3) & 0x70));
        }

    float d[2][8][4];
#pragma unroll
    for (int f = 0; f < 2; f++)
#pragma unroll
        for (int g = 0; g < 8; g++)
#pragma unroll
            for (int e = 0; e < 4; e++) d[f][g][e] = 0.f;

    // frag address components
    const int l7  = lane & 7;
    const int am  = wm * 32 + l7 + ((lane >> 3) & 1) * 8;   // + f*16
    const int aku = (lane >> 4) & 1;
    const int bn  = wn * 64 + ((lane >> 4) << 3) + l7;      // + pair*16
    const int bku = (lane >> 3) & 1;

    const int nkt = K / GBK;     // 32

    // prologue: stage tile 0
    {
        const uint32_t base = sb;
#pragma unroll
        for (int p = 0; p < 4; p++)
#pragma unroll
            for (int j = 0; j < 4; j++)
                CP_ASYNC16(base + dsts[p][j], srcs[p] + (ucb + j) * 8);
        CP_COMMIT();
    }

    for (int kt = 0; kt < nkt; kt++) {
        if (kt + 1 < nkt) {
            const uint32_t base = sb + ((kt + 1) & 1) * STAGE_B;
            const int ko = (kt + 1) * GBK;
#pragma unroll
            for (int p = 0; p < 4; p++)
#pragma unroll
                for (int j = 0; j < 4; j++)
                    CP_ASYNC16(base + dsts[p][j], srcs[p] + ko + (ucb + j) * 8);
            CP_COMMIT();
            CP_WAIT1();
        } else {
            CP_WAIT0();
        }
        __syncthreads();

        const uint32_t ab  = sb + (kt & 1) * STAGE_B;
        const uint32_t alb = ab + PLANE_B;
        const uint32_t wb  = ab + 2 * PLANE_B;
        const uint32_t wlb = ab + 3 * PLANE_B;

#pragma unroll
        for (int kk = 0; kk < 4; kk++) {
            uint32_t a0[4], a1[4], q0[4], q1[4];
            const uint32_t kxa = (uint32_t)(((kk * 2 + aku) ^ l7) * 16);
            LDSM_X4(a0, ab  +  am       * 128 + kxa);
            LDSM_X4(a1, ab  + (am + 16) * 128 + kxa);
            LDSM_X4(q0, alb +  am       * 128 + kxa);
            LDSM_X4(q1, alb + (am + 16) * 128 + kxa);
            const uint32_t kxb = (uint32_t)(((kk * 2 + bku) ^ l7) * 16);
#pragma unroll
            for (int p = 0; p < 4; p++) {
                uint32_t bh[4], bl[4];
                LDSM_X4(bh, wb  + (bn + p * 16) * 128 + kxb);
                LDSM_X4(bl, wlb + (bn + p * 16) * 128 + kxb);
                MMA16816(d[0][2*p],     a0, bh[0], bh[1]);
                MMA16816(d[0][2*p],     a0, bl[0], bl[1]);
                MMA16816(d[0][2*p],     q0, bh[0], bh[1]);
                MMA16816(d[0][2*p + 1], a0, bh[2], bh[3]);
                MMA16816(d[0][2*p + 1], a0, bl[2], bl[3]);
                MMA16816(d[0][2*p + 1], q0, bh[2], bh[3]);
                MMA16816(d[1][2*p],     a1, bh[0], bh[1]);
                MMA16816(d[1][2*p],     a1, bl[0], bl[1]);
                MMA16816(d[1][2*p],     q1, bh[0], bh[1]);
                MMA16816(d[1][2*p + 1], a1, bh[2], bh[3]);
                MMA16816(d[1][2*p + 1], a1, bl[2], bl[3]);
                MMA16816(d[1][2*p + 1], q1, bh[2], bh[3]);
            }
        }
        __syncthreads();
    }

    // ---- epilogue ----
    const int grp  = lane >> 2;
    const int tig2 = (lane & 3) * 2;
#pragma unroll
    for (int f = 0; f < 2; f++) {
        const int row = row0 + wm * 32 + f * 16 + grp;
#pragma unroll
        for (int g = 0; g < 8; g++) {
            const int col = col0 + wn * 64 + g * 8 + tig2;
            *(float2*)(C + (size_t)row * N + col) =
                make_float2(d[f][g][0], d[f][g][1]);
            *(float2*)(C + (size_t)(row + 8) * N + col) =
                make_float2(d[f][g][2], d[f][g][3]);
        }
    }
}

// =====================================================================
// Interleaved RoPE in-place on (BT, nh, 32).
// =====================================================================
__global__ void rope_kernel(float* __restrict__ x,
                            const float* __restrict__ cs,
                            const float* __restrict__ sn, int nh)
{
    int idx = blockIdx.x * 256 + threadIdx.x;
    int total = BTc * nh * (HDc / 2);
    if (idx >= total) return;
    int p    = idx & (HDc / 2 - 1);
    int rest = idx >> 4;
    int h    = rest % nh;
    int row  = rest / nh;
    int t    = row & (Tc - 1);
    float c = cs[t * (HDc / 2) + p];
    float s = sn[t * (HDc / 2) + p];
    float* ptr = x + ((size_t)row * nh + h) * HDc + 2 * p;
    float x1 = ptr[0], x2 = ptr[1];
    ptr[0] = x1 * c - x2 * s;
    ptr[1] = x1 * s + x2 * c;
}

// =====================================================================
// Fused 4-ensemble flash attention + RMSNorm (unchanged from R2).
// =====================================================================
#define QS        (64*33)
#define SQ_FLOATS (4*QS)
#define SP_STRIDE 66
#define SP_FLOATS (64*SP_STRIDE)
#define SV_FLOATS (64*128)
#define X_FLOATS  (SP_FLOATS + SV_FLOATS)
#define FL_SMEM   ((SQ_FLOATS + X_FLOATS + 2*4*64) * 4)

__global__ __launch_bounds__(256, 2) void flash_kernel(
    const float* __restrict__ Q, const float* __restrict__ Kb,
    const float* __restrict__ Vb, const float* __restrict__ rawmap,
    const float* __restrict__ wscale, const float* __restrict__ gamma,
    float* __restrict__ Out)
{
    extern __shared__ float sm[];
    float* sQ   = sm;
    float* sX   = sm + SQ_FLOATS;
    float* sStM = sX + X_FLOATS;
    float* sStI = sStM + 4 * 64;

    const int qt  = gridDim.x - 1 - blockIdx.x;
    const int h   = blockIdx.y;
    const int b   = blockIdx.z;
    const int hkv = h >> 2;
    const int tid = threadIdx.x;
    const int tx  = tid & 15;
    const int ty  = tid >> 4;
    const int tx4 = tx * 4;
    const int ty4 = ty * 4;
    const int q0  = qt * 64;
    const float scale = 0.17677669529663687f;

#pragma unroll
    for (int u = 0; u < 8; u++) {
        int fi = u * 256 + tid;
        int m  = fi >> 9;
        int lr = (fi >> 3) & 63;
        int c4 = (fi & 7) * 4;
        float4 v4 = *(const float4*)(Q +
            ((size_t)(b * Tc + q0 + lr) * 64 + (h * 4 + m)) * HDc + c4);
        float* dst = sQ + m * QS + lr * 33 + c4;
        dst[0] = v4.x; dst[1] = v4.y; dst[2] = v4.z; dst[3] = v4.w;
    }

    float mapw[4];
#pragma unroll
    for (int m = 0; m < 4; m++) mapw[m] = tanhf(rawmap[m]) * wscale[0];

    float RM[4][4], RS[4][4];
#pragma unroll
    for (int m = 0; m < 4; m++)
#pragma unroll
        for (int r = 0; r < 4; r++) { RM[m][r] = -1e30f; RS[m][r] = 0.f; }

    for (int jt = 0; jt <= qt; jt++) {
        const int k0 = jt * 64;
        __syncthreads();
#pragma unroll
        for (int u = 0; u < 8; u++) {
            int fi = u * 256 + tid;
            int m  = fi >> 9;
            int lr = (fi >> 3) & 63;
            int c4 = (fi & 7) * 4;
            float4 v4 = *(const float4*)(Kb +
                ((size_t)(b * Tc + k0 + lr) * 16 + (hkv * 4 + m)) * HDc + c4);
            float* dst = sX + m * QS + lr * 33 + c4;
            dst[0] = v4.x; dst[1] = v4.y; dst[2] = v4.z; dst[3] = v4.w;
        }
        __syncthreads();
        const bool diag = (jt == qt);

        for (int m = 0; m < 4; m++) {
            const float* Qp = sQ + m * QS + ty4 * 33;
            const float* Kp = sX + m * QS + tx4 * 33;
            float S[4][4];
#pragma unroll
            for (int r = 0; r < 4; r++)
#pragma unroll
                for (int c = 0; c < 4; c++) S[r][c] = 0.f;
#pragma unroll 8
            for (int d = 0; d < 32; d++) {
                float a0 = Qp[d], a1 = Qp[33 + d], a2 = Qp[66 + d], a3 = Qp[99 + d];
                float b0 = Kp[d], b1 = Kp[33 + d], b2 = Kp[66 + d], b3 = Kp[99 + d];
                S[0][0] += a0 * b0; S[0][1] += a0 * b1; S[0][2] += a0 * b2; S[0][3] += a0 * b3;
                S[1][0] += a1 * b0; S[1][1] += a1 * b1; S[1][2] += a1 * b2; S[1][3] += a1 * b3;
                S[2][0] += a2 * b0; S[2][1] += a2 * b1; S[2][2] += a2 * b2; S[2][3] += a2 * b3;
                S[3][0] += a3 * b0; S[3][1] += a3 * b1; S[3][2] += a3 * b2; S[3][3] += a3 * b3;
            }
#pragma unroll
            for (int r = 0; r < 4; r++) {
#pragma unroll
                for (int c = 0; c < 4; c++) {
                    float s = S[r][c] * scale;
                    if (diag && (k0 + tx4 + c > q0 + ty4 + r)) s = -1e30f;
                    S[r][c] = s;
                }
                float tm = fmaxf(fmaxf(S[r][0], S[r][1]), fmaxf(S[r][2], S[r][3]));
#pragma unroll
                for (int o = 1; o < 16; o <<= 1)
                    tm = fmaxf(tm, __shfl_xor_sync(0xffffffffu, tm, o));
                float mnew = fmaxf(RM[m][r], tm);
                float corr = __expf(RM[m][r] - mnew);
                float ps = __expf(S[r][0] - mnew) + __expf(S[r][1] - mnew)
                         + __expf(S[r][2] - mnew) + __expf(S[r][3] - mnew);
#pragma unroll
                for (int o = 1; o < 16; o <<= 1)
                    ps += __shfl_xor_sync(0xffffffffu, ps, o);
                RS[m][r] = RS[m][r] * corr + ps;
                RM[m][r] = mnew;
            }
        }
    }

    __syncthreads();
    if (tx == 0) {
#pragma unroll
        for (int m = 0; m < 4; m++)
#pragma unroll
            for (int r = 0; r < 4; r++) {
                sStM[m * 64 + ty4 + r] = RM[m][r];
                sStI[m * 64 + ty4 + r] = mapw[m] / RS[m][r];
            }
    }
    __syncthreads();

    float acc[4][8];
#pragma unroll
    for (int r = 0; r < 4; r++)
#pragma unroll
        for (int c = 0; c < 8; c++) acc[r][c] = 0.f;

    for (int jt = 0; jt <= qt; jt++) {
        const int k0 = jt * 64;
        __syncthreads();
#pragma unroll
        for (int u = 0; u < 8; u++) {
            int fi = u * 256 + tid;
            int m  = fi >> 9;
            int lr = (fi >> 3) & 63;
            int c4 = (fi & 7) * 4;
            float4 v4 = *(const float4*)(Kb +
                ((size_t)(b * Tc + k0 + lr) * 16 + (hkv * 4 + m)) * HDc + c4);
            float* dst = sX + m * QS + lr * 33 + c4;
            dst[0] = v4.x; dst[1] = v4.y; dst[2] = v4.z; dst[3] = v4.w;
        }
        __syncthreads();
        const bool diag = (jt == qt);

        float P[4][4];
#pragma unroll
        for (int r = 0; r < 4; r++)
#pragma unroll
            for (int c = 0; c < 4; c++) P[r][c] = 0.f;

        for (int m = 0; m < 4; m++) {
            const float* Qp = sQ + m * QS + ty4 * 33;
            const float* Kp = sX + m * QS + tx4 * 33;
            float S[4][4];
#pragma unroll
            for (int r = 0; r < 4; r++)
#pragma unroll
                for (int c = 0; c < 4; c++) S[r][c] = 0.f;
#pragma unroll 8
            for (int d = 0; d < 32; d++) {
                float a0 = Qp[d], a1 = Qp[33 + d], a2 = Qp[66 + d], a3 = Qp[99 + d];
                float b0 = Kp[d], b1 = Kp[33 + d], b2 = Kp[66 + d], b3 = Kp[99 + d];
                S[0][0] += a0 * b0; S[0][1] += a0 * b1; S[0][2] += a0 * b2; S[0][3] += a0 * b3;
                S[1][0] += a1 * b0; S[1][1] += a1 * b1; S[1][2] += a1 * b2; S[1][3] += a1 * b3;
                S[2][0] += a2 * b0; S[2][1] += a2 * b1; S[2][2] += a2 * b2; S[2][3] += a2 * b3;
                S[3][0] += a3 * b0; S[3][1] += a3 * b1; S[3][2] += a3 * b2; S[3][3] += a3 * b3;
            }
#pragma unroll
            for (int r = 0; r < 4; r++) {
                float sm_ = sStM[m * 64 + ty4 + r];
                float si  = sStI[m * 64 + ty4 + r];
#pragma unroll
                for (int c = 0; c < 4; c++) {
                    float s = S[r][c] * scale;
                    if (diag && (k0 + tx4 + c > q0 + ty4 + r)) s = -1e30f;
                    P[r][c] += si * __expf(s - sm_);
                }
            }
        }
        __syncthreads();

#pragma unroll
        for (int r = 0; r < 4; r++)
#pragma unroll
            for (int c = 0; c < 4; c++)
                sX[(ty4 + r) * SP_STRIDE + tx4 + c] = P[r][c];
#pragma unroll
        for (int u = 0; u < 8; u++) {
            int fi = u * 256 + tid;
            int lr = fi >> 5;
            int c4 = (fi & 31) * 4;
            *(float4*)(sX + SP_FLOATS + lr * 128 + c4) = *(const float4*)(Vb +
                ((size_t)(b * Tc + k0 + lr) * HKVc + hkv) * DVc + c4);
        }
        __syncthreads();

        const float* Pp = sX + ty4 * SP_STRIDE;
        const float* Vp = sX + SP_FLOATS;
#pragma unroll 8
        for (int kk = 0; kk < 64; kk++) {
            float a0 = Pp[kk], a1 = Pp[SP_STRIDE + kk],
                  a2 = Pp[2 * SP_STRIDE + kk], a3 = Pp[3 * SP_STRIDE + kk];
            float4 bl = *(const float4*)(Vp + kk * 128 + tx4);
            float4 bh = *(const float4*)(Vp + kk * 128 + 64 + tx4);
            acc[0][0] += a0 * bl.x; acc[0][1] += a0 * bl.y; acc[0][2] += a0 * bl.z; acc[0][3] += a0 * bl.w;
            acc[0][4] += a0 * bh.x; acc[0][5] += a0 * bh.y; acc[0][6] += a0 * bh.z; acc[0][7] += a0 * bh.w;
            acc[1][0] += a1 * bl.x; acc[1][1] += a1 * bl.y; acc[1][2] += a1 * bl.z; acc[1][3] += a1 * bl.w;
            acc[1][4] += a1 * bh.x; acc[1][5] += a1 * bh.y; acc[1][6] += a1 * bh.z; acc[1][7] += a1 * bh.w;
            acc[2][0] += a2 * bl.x; acc[2][1] += a2 * bl.y; acc[2][2] += a2 * bl.z; acc[2][3] += a2 * bl.w;
            acc[2][4] += a2 * bh.x; acc[2][5] += a2 * bh.y; acc[2][6] += a2 * bh.z; acc[2][7] += a2 * bh.w;
            acc[3][0] += a3 * bl.x; acc[3][1] += a3 * bl.y; acc[3][2] += a3 * bl.z; acc[3][3] += a3 * bl.w;
            acc[3][4] += a3 * bh.x; acc[3][5] += a3 * bh.y; acc[3][6] += a3 * bh.z; acc[3][7] += a3 * bh.w;
        }
    }

    float4 g0 = *(const float4*)(gamma + tx4);
    float4 g1 = *(const float4*)(gamma + 64 + tx4);
#pragma unroll
    for (int r = 0; r < 4; r++) {
        float ss = 0.f;
#pragma unroll
        for (int c = 0; c < 8; c++) ss += acc[r][c] * acc[r][c];
#pragma unroll
        for (int o = 1; o < 16; o <<= 1)
            ss += __shfl_xor_sync(0xffffffffu, ss, o);
        float rs = rsqrtf(ss * (1.f / 128.f) + 1e-5f);
        float* dst = Out + ((size_t)(b * Tc + q0 + ty4 + r) * Hc + h) * DVc;
        *(float4*)(dst + tx4) = make_float4(
            acc[r][0] * rs * g0.x, acc[r][1] * rs * g0.y,
            acc[r][2] * rs * g0.z, acc[r][3] * rs * g0.w);
        *(float4*)(dst + 64 + tx4) = make_float4(
            acc[r][4] * rs * g1.x, acc[r][5] * rs * g1.y,
            acc[r][6] * rs * g1.z, acc[r][7] * rs * g1.w);
    }
}

// =====================================================================
extern "C" void kernel_launch(void* const* d_in, const int* in_sizes, int n_in,
                              void* d_out, int out_size)
{
    (void)in_sizes; (void)n_in; (void)out_size;
    const float* x      = (const float*)d_in[0];
    const float* cosb   = (const float*)d_in[1];
    const float* sinb   = (const float*)d_in[2];
    const float* q_w    = (const float*)d_in[3];
    const float* k_w    = (const float*)d_in[4];
    const float* v_w    = (const float*)d_in[5];
    const float* out_w  = (const float*)d_in[6];
    const float* rawmap = (const float*)d_in[7];
    const float* wscale = (const float*)d_in[8];
    const float* gamma  = (const float*)d_in[9];

    float *qp, *kp, *vp, *cp;
    __half *x2, *wq2, *wk2, *wv2, *wo2;
    cudaGetSymbolAddress((void**)&qp, g_q);
    cudaGetSymbolAddress((void**)&kp, g_k);
    cudaGetSymbolAddress((void**)&vp, g_v);
    cudaGetSymbolAddress((void**)&cp, g_comb);
    cudaGetSymbolAddress((void**)&x2, g_x2);
    cudaGetSymbolAddress((void**)&wq2, g_wq2);
    cudaGetSymbolAddress((void**)&wk2, g_wk2);
    cudaGetSymbolAddress((void**)&wv2, g_wv2);
    cudaGetSymbolAddress((void**)&wo2, g_wo2);

    cudaFuncSetAttribute(flash_kernel,
                         cudaFuncAttributeMaxDynamicSharedMemorySize, FL_SMEM);
    cudaFuncSetAttribute(hgemm3,
                         cudaFuncAttributeMaxDynamicSharedMemorySize, G_SMEM);

    const size_t xplane = (size_t)BTc * Ec;
    const size_t wqn    = (size_t)Ec * Ec;
    const size_t wkn    = (size_t)KVE * Ec;

    // ---- limb splits ----
    split2_kernel<<<(unsigned)((xplane / 2 + 255) / 256), 256>>>(x, x2, xplane / 2, xplane);
    split2_kernel<<<(unsigned)((wqn / 2 + 255) / 256), 256>>>(q_w, wq2, wqn / 2, wqn);
    split2_kernel<<<(unsigned)((wkn / 2 + 255) / 256), 256>>>(k_w, wk2, wkn / 2, wkn);
    split2_kernel<<<(unsigned)((wkn / 2 + 255) / 256), 256>>>(v_w, wv2, wkn / 2, wkn);
    split2_kernel<<<(unsigned)((wqn / 2 + 255) / 256), 256>>>(out_w, wo2, wqn / 2, wqn);

    // ---- projections (HMMA 3-pass) ----
    hgemm3<<<dim3(Ec / 128, BTc / 128, 1), 256, G_SMEM>>>(
        x2, xplane, wq2, qp, wq2, qp, Ec, Ec);
    hgemm3<<<dim3(KVE / 128, BTc / 128, 2), 256, G_SMEM>>>(
        x2, xplane, wk2, kp, wv2, vp, KVE, Ec);

    // ---- RoPE ----
    {
        int tq = BTc * (Hc * Mc) * (HDc / 2);
        int tk = BTc * (HKVc * Mc) * (HDc / 2);
        rope_kernel<<<(tq + 255) / 256, 256>>>(qp, cosb, sinb, Hc * Mc);
        rope_kernel<<<(tk + 255) / 256, 256>>>(kp, cosb, sinb, HKVc * Mc);
    }

    // ---- fused flash attention + RMSNorm ----
    flash_kernel<<<dim3(Tc / 64, Hc, Bc), 256, FL_SMEM>>>(
        qp, kp, vp, rawmap, wscale, gamma, cp);

    // ---- split combined, output projection ----
    split2_kernel<<<(unsigned)((xplane / 2 + 255) / 256), 256>>>(cp, x2, xplane / 2, xplane);
    hgemm3<<<dim3(Ec / 128, BTc / 128, 1), 256, G_SMEM>>>(
        x2, xplane, wo2, (float*)d_out, wo2, (float*)d_out, Ec, Ec);
}